// round 17
// baseline (speedup 1.0000x reference)
#include <cuda_runtime.h>
#include <cuda_bf16.h>
#include <math.h>
#include <stdint.h>

// ---------------- problem constants ----------------
#define Bsz   8
#define Tfull 1600
#define Dm    512
#define DIc   1024
#define Nst   16
#define Ll    8
#define Vv    1024
#define T4    400
#define M4    (Bsz*T4)    // 3200
#define M2    (Bsz*800)   // 6400

// ---------------- scratch (single __device__ array, ~183MB) ----------------
__device__ float g_buf[45801472];

// offsets in floats
#define OFF_FEATSPA  0
#define OFF_OUT1P    1638400
#define OFF_XN_T     4923392
#define OFF_XZ       6561792
#define OFF_XI_T     16392192
#define OFF_DT       19668992
#define OFF_PROJ     22945792
#define OFF_PROJ_T   23150592
#define OFF_YC_T     23355392
#define OFF_X        26632192
#define OFF_X_T      28270592
#define OFF_W1T      29908992
#define OFF_W2T      30040064
#define OFF_INW      30826496
#define OFF_XW       39215104
#define OFF_DTW      39739392
#define OFF_OUTW     40263680
#define OFF_HEADW    44457984
#define OFF_XPART    44982272

// layer weight sizes in bf16 elements
#define S0E (2048*1024)
#define S1E (64*2048)
#define S2E (1024*128)
#define S3E (512*2048)
#define SLAYER (S0E+S1E+S2E+S3E)   // 3407872

// prep_all region sizes
#define R_W1   (512*512)
#define R_W2   (512*3072)
#define R_C1A  (M2*512)
#define R_ZP   (Bsz*2*1024)
#define R_HEAD (1024*1024)
#define R_LAY  (Ll*SLAYER)
#define R_TOT  (R_W1+R_W2+R_C1A+R_ZP+R_HEAD+R_LAY)

// ---------------- math helpers ----------------
__device__ __forceinline__ float gelu_f(float x) {
    return 0.5f * x * (1.0f + erff(x * 0.70710678118654752f));
}
__device__ __forceinline__ float softplus_f(float x) {
    return fmaxf(x, 0.0f) + log1pf(expf(-fabsf(x)));
}
__device__ __forceinline__ __nv_bfloat16 planeval(float v, int plane) {
    __nv_bfloat16 h = __float2bfloat16(v);
    if (plane == 0) return h;
    return __float2bfloat16(v - __bfloat162float(h));
}
__device__ __forceinline__ void planewrite(float v, __nv_bfloat16* buf, long long base) {
    __nv_bfloat16 h = __float2bfloat16(v);
    buf[base] = h;
    buf[base + 64] = __float2bfloat16(v - __bfloat162float(h));
}

// ---------------- PTX helpers ----------------
__device__ __forceinline__ uint32_t smem_u32(const void* p) {
    uint32_t a;
    asm("{ .reg .u64 t; cvta.to.shared.u64 t, %1; cvt.u32.u64 %0, t; }" : "=r"(a) : "l"(p));
    return a;
}
#define SW128(x) ((x) ^ (((x) >> 3) & 0x70))
__device__ __forceinline__ void cp16(uint32_t dst, const void* src) {
    asm volatile("cp.async.cg.shared.global [%0], [%1], 16;" :: "r"(dst), "l"(src) : "memory");
}
__device__ __forceinline__ void ldsm4(uint32_t* r, uint32_t addr) {
    asm volatile("ldmatrix.sync.aligned.m8n8.x4.shared.b16 {%0,%1,%2,%3}, [%4];"
                 : "=r"(r[0]), "=r"(r[1]), "=r"(r[2]), "=r"(r[3]) : "r"(addr));
}
__device__ __forceinline__ void mma16(float* c, const uint32_t* a, const uint32_t* b) {
    asm volatile(
        "mma.sync.aligned.m16n8k16.row.col.f32.bf16.bf16.f32 "
        "{%0,%1,%2,%3},{%4,%5,%6,%7},{%8,%9},{%0,%1,%2,%3};"
        : "+f"(c[0]), "+f"(c[1]), "+f"(c[2]), "+f"(c[3])
        : "r"(a[0]), "r"(a[1]), "r"(a[2]), "r"(a[3]), "r"(b[0]), "r"(b[1]));
}

// ---------------- bf16 tensor-core GEMM (hi/md planes, BM=64, BN=64|128) -------
// Data per row: K/64 blocks of 256B: [128B hi | 128B md]. Row pitch in ELEMENTS.
// Per chunk: mma(ahi,bhi) + mma(ahi,bmd) + mma(amd,bhi).  NC = K/64.
// 2-stage pipeline. BN=64: 3 CTAs/SM. BN=128: 2 CTAs/SM, warp tile 32x32.
template<int BN>
__global__ void __launch_bounds__(256, (BN == 64) ? 3 : 2) bgemm_k(
        const __nv_bfloat16* __restrict__ A,
        const __nv_bfloat16* __restrict__ Bw,
        const float* __restrict__ bias,
        void* __restrict__ Cv,
        int NC, int bpitch,
        int a_rpb, long long a_bs, int a_rs,
        int o_rpb, long long o_bs, int o_rs,
        int act, int outmode, int accum,
        int ksplit, long long zoff) {
    extern __shared__ char smem_raw[];
    uint32_t sb = (smem_u32(smem_raw) + 1023) & ~1023u;
    constexpr uint32_t BSTG = (uint32_t)BN * 128u;        // one B plane
    constexpr uint32_t STG = 16384u + 2u * BSTG;          // A(hi|md) + B(hi|md)
    constexpr int WN = BN / 4;                            // warp n-strip width
    constexpr int NT = WN / 8;                            // n8 tiles per warp
    constexpr int BG = BN / 16;                           // B granules per thread

    int tid = threadIdx.x, wid = tid >> 5, lane = tid & 31;
    int bm = blockIdx.y * 64, bn = blockIdx.x * BN;
    int c0 = blockIdx.z * ksplit;
    int c1 = min(NC, c0 + ksplit);

    const char* aptr0; int adel[4]; uint32_t adst[4];
    const char* bptr0; int bdel[BG]; uint32_t bdst[BG];
    {
        long long aref = 0;
#pragma unroll
        for (int i = 0; i < 4; i++) {
            int G = tid + i * 256;
            int row = G >> 4, sub = G & 15;
            int gm = bm + row;
            long long off = 2 * ((long long)(gm / a_rpb) * a_bs + (long long)(gm % a_rpb) * a_rs)
                          + sub * 16;
            if (i == 0) { aref = off; aptr0 = (const char*)A + off; }
            adel[i] = (int)(off - aref);
            adst[i] = (uint32_t)((sub >> 3) * 8192) + SW128((uint32_t)(row * 128 + (sub & 7) * 16));
        }
        long long bref = 0;
#pragma unroll
        for (int i = 0; i < BG; i++) {
            int G = tid + i * 256;
            int row = G >> 4, sub = G & 15;
            long long off = 2LL * (bn + row) * bpitch + sub * 16;
            if (i == 0) { bref = off; bptr0 = (const char*)Bw + off; }
            bdel[i] = (int)(off - bref);
            bdst[i] = 16384u + (uint32_t)(sub >> 3) * BSTG + SW128((uint32_t)(row * 128 + (sub & 7) * 16));
        }
    }

    auto issue = [&](int c) {
        uint32_t base = sb + (uint32_t)(c & 1) * STG;
        const char* ap = aptr0 + (long long)c * 256;
        const char* bp = bptr0 + (long long)c * 256;
#pragma unroll
        for (int i = 0; i < 4; i++) cp16(base + adst[i], ap + adel[i]);
#pragma unroll
        for (int i = 0; i < BG; i++) cp16(base + bdst[i], bp + bdel[i]);
        asm volatile("cp.async.commit_group;" ::: "memory");
    };

    int wm = wid & 1, wn = wid >> 1;
    float acc[2][NT][4];
#pragma unroll
    for (int i = 0; i < 2; i++)
#pragma unroll
        for (int j = 0; j < NT; j++)
#pragma unroll
            for (int r = 0; r < 4; r++) acc[i][j][r] = 0.0f;

    uint32_t arp[2], atsw[2];
    {
        int a_trow = (lane & 7) + ((lane >> 3) & 1) * 8;
        uint32_t a_tcol = (uint32_t)((lane >> 4) * 16);
#pragma unroll
        for (int i = 0; i < 2; i++) {
            uint32_t rp = (uint32_t)((wm * 32 + i * 16 + a_trow) * 128);
            arp[i] = rp;
            atsw[i] = a_tcol ^ ((rp >> 3) & 0x70);
        }
    }
    uint32_t brp[NT / 2], btsw[NT / 2];
    {
        int b_trow = ((lane >> 4) << 3) + (lane & 7);
        uint32_t b_tcol = (uint32_t)(((lane >> 3) & 1) * 16);
#pragma unroll
        for (int jp = 0; jp < NT / 2; jp++) {
            uint32_t rp = (uint32_t)((wn * WN + jp * 16 + b_trow) * 128);
            brp[jp] = rp;
            btsw[jp] = b_tcol ^ ((rp >> 3) & 0x70);
        }
    }

    issue(c0);
    if (c0 + 1 < c1) issue(c0 + 1);

    for (int c = c0; c < c1; c++) {
        if (c + 1 < c1) asm volatile("cp.async.wait_group 1;" ::: "memory");
        else            asm volatile("cp.async.wait_group 0;" ::: "memory");
        __syncthreads();

        uint32_t base = sb + (uint32_t)(c & 1) * STG;
        uint32_t abase0 = base + arp[0];
        uint32_t abase1 = base + arp[1];
        uint32_t bbase  = base + 16384u;
#pragma unroll
        for (int ks = 0; ks < 4; ks++) {
            uint32_t klo = (uint32_t)(ks << 5);
            uint32_t ahi[2][4], amd[2][4];
            {
                uint32_t lo0 = klo ^ atsw[0];
                ldsm4(ahi[0], abase0 + lo0);
                ldsm4(amd[0], abase0 + 8192u + lo0);
                uint32_t lo1 = klo ^ atsw[1];
                ldsm4(ahi[1], abase1 + lo1);
                ldsm4(amd[1], abase1 + 8192u + lo1);
            }
            uint32_t bhi[NT][2], bmd[NT][2];
#pragma unroll
            for (int jp = 0; jp < NT / 2; jp++) {
                uint32_t lob = brp[jp] + (klo ^ btsw[jp]);
                uint32_t r[4];
                ldsm4(r, bbase + lob);
                bhi[2 * jp][0] = r[0]; bhi[2 * jp][1] = r[1];
                bhi[2 * jp + 1][0] = r[2]; bhi[2 * jp + 1][1] = r[3];
                ldsm4(r, bbase + BSTG + lob);
                bmd[2 * jp][0] = r[0]; bmd[2 * jp][1] = r[1];
                bmd[2 * jp + 1][0] = r[2]; bmd[2 * jp + 1][1] = r[3];
            }
#pragma unroll
            for (int i = 0; i < 2; i++)
#pragma unroll
                for (int j = 0; j < NT; j++) {
                    mma16(acc[i][j], ahi[i], bhi[j]);
                    mma16(acc[i][j], ahi[i], bmd[j]);
                    mma16(acc[i][j], amd[i], bhi[j]);
                }
        }

        if (c + 2 < c1) {
            __syncthreads();
            issue(c + 2);
        }
    }

    // epilogue
    float* Cz = (float*)Cv + blockIdx.z * zoff;
#pragma unroll
    for (int i = 0; i < 2; i++) {
#pragma unroll
        for (int h = 0; h < 2; h++) {
            int gm = bm + wm * 32 + i * 16 + (lane >> 2) + h * 8;
            long long orow = (long long)(gm / o_rpb) * o_bs + (long long)(gm % o_rpb) * o_rs;
#pragma unroll
            for (int j = 0; j < NT; j++) {
                int gn = bn + wn * WN + j * 8 + (lane & 3) * 2;
#pragma unroll
                for (int e = 0; e < 2; e++) {
                    float v = acc[i][j][h * 2 + e];
                    int gne = gn + e;
                    if (bias) v += bias[gne];
                    if (act == 1) v = gelu_f(v);
                    else if (act == 2) v = softplus_f(v);
                    if (outmode == 0) {
                        long long o = orow + gne;
                        if (accum) v += Cz[o];
                        Cz[o] = v;
                    } else {
                        __nv_bfloat16* C = (__nv_bfloat16*)Cv;
                        long long o = orow + ((gne >> 6) * 128 + (gne & 63));
                        planewrite(v, C, o);
                    }
                }
            }
        }
    }
}

// ---------------- ONE fused prep/conversion kernel ----------------
__global__ void prep_all_k(const float* __restrict__ feats,
                           const float* __restrict__ conv1_w,
                           const float* __restrict__ conv2_w,
                           const float* __restrict__ head_w,
                           const float* __restrict__ in_proj,
                           const float* __restrict__ x_proj,
                           const float* __restrict__ dt_w,
                           const float* __restrict__ out_proj,
                           __nv_bfloat16* __restrict__ w1t,
                           __nv_bfloat16* __restrict__ w2t,
                           __nv_bfloat16* __restrict__ fa,
                           __nv_bfloat16* __restrict__ out1p,
                           __nv_bfloat16* __restrict__ headW,
                           __nv_bfloat16* __restrict__ inW,
                           __nv_bfloat16* __restrict__ xW,
                           __nv_bfloat16* __restrict__ dtW,
                           __nv_bfloat16* __restrict__ outW) {
    long long i = (long long)blockIdx.x * 256 + threadIdx.x;
    if (i >= R_TOT) return;
    if (i < R_W1) {
        int n = (int)(i >> 9), e = (int)(i & 511);
        int sub = e & 127, plane = sub >> 6;
        int k = (e >> 7) * 64 + (sub & 63);
        float val = 0.0f;
        if (k < 240) val = conv1_w[n * 240 + (k % 80) * 3 + (k / 80)];
        w1t[i] = planeval(val, plane);
        return;
    }
    i -= R_W1;
    if (i < R_W2) {
        int n = (int)(i / 3072), e = (int)(i % 3072);
        int sub = e & 127, plane = sub >> 6;
        int k = (e >> 7) * 64 + (sub & 63);
        int tap = k / 512, c = k & 511;
        w2t[i] = planeval(conv2_w[n * 1536 + c * 3 + tap], plane);
        return;
    }
    i -= R_W2;
    if (i < R_C1A) {
        int m = (int)(i >> 9), e = (int)(i & 511);
        int sub = e & 127, plane = sub >> 6;
        int k = (e >> 7) * 64 + (sub & 63);
        float val = 0.0f;
        if (k < 240) {
            int tap = k / 80, c = k % 80;
            int b = m / 800, p = m % 800;
            int tin = 2 * p - 1 + tap;
            if (tin >= 0 && tin < 1600)
                val = feats[((long long)b * 1600 + tin) * 80 + c];
        }
        fa[i] = planeval(val, plane);
        return;
    }
    i -= R_C1A;
    if (i < R_ZP) {
        int e = (int)(i & 1023); int r = (int)(i >> 10);
        int b = r >> 1; int t = (r & 1) ? 801 : 0;
        out1p[(long long)(b * 802 + t) * 1024 + e] = __float2bfloat16(0.0f);
        return;
    }
    i -= R_ZP;
    if (i < R_HEAD) {
        int n = (int)(i >> 10), e = (int)(i & 1023);
        int sub = e & 127, plane = sub >> 6;
        int k = (e >> 7) * 64 + (sub & 63);
        headW[i] = planeval(head_w[k * 1024 + n], plane);
        return;
    }
    i -= R_HEAD;
    int li = (int)(i / SLAYER);
    long long r = i % SLAYER;
    const float* inw = in_proj + (long long)li * Dm * 2048;
    const float* xw  = x_proj + (long long)li * DIc * 64;
    const float* dtw = dt_w + (long long)li * 32 * DIc;
    const float* outw= out_proj + (long long)li * DIc * Dm;
    if (r < S0E) {
        int n = (int)(r >> 10), e = (int)(r & 1023);
        int sub = e & 127, plane = sub >> 6;
        int k = (e >> 7) * 64 + (sub & 63);
        inW[(long long)li * S0E + r] = planeval(inw[k * 2048 + n], plane);
        return;
    }
    r -= S0E;
    if (r < S1E) {
        int n = (int)(r >> 11), e = (int)(r & 2047);
        int sub = e & 127, plane = sub >> 6;
        int k = (e >> 7) * 64 + (sub & 63);
        xW[(long long)li * S1E + r] = planeval(xw[k * 64 + n], plane);
        return;
    }
    r -= S1E;
    if (r < S2E) {
        int n = (int)(r >> 7), e = (int)(r & 127);
        int plane = e >> 6, k = e & 63;
        float val = (k < 32) ? dtw[k * 1024 + n] : 0.0f;
        dtW[(long long)li * S2E + r] = planeval(val, plane);
        return;
    }
    r -= S2E;
    {
        int n = (int)(r >> 11), e = (int)(r & 2047);
        int sub = e & 127, plane = sub >> 6;
        int k = (e >> 7) * 64 + (sub & 63);
        outW[(long long)li * S3E + r] = planeval(outw[k * 512 + n], plane);
    }
}

// ---------------- split-K combine -> proj f32 + proj_t planes ----------------
__global__ void xcomb_k(const float* __restrict__ parts, float* __restrict__ proj,
                        __nv_bfloat16* __restrict__ pt) {
    int i = blockIdx.x * 256 + threadIdx.x;
    if (i >= M4 * 128) return;
    int m = i >> 7, e = i & 127;
    if (e < 64) {
        int o = m * 64 + e;
        proj[o] = parts[o] + parts[204800 + o] + parts[2 * 204800 + o] + parts[3 * 204800 + o];
    }
    int plane = e >> 6, k = e & 63;
    float v = 0.0f;
    if (k < 32) {
        int o = m * 64 + k;
        v = parts[o] + parts[204800 + o] + parts[2 * 204800 + o] + parts[3 * 204800 + o];
    }
    pt[i] = planeval(v, plane);
}

__global__ void x_t_k(const float* __restrict__ x, __nv_bfloat16* __restrict__ xt) {
    int i = blockIdx.x * 256 + threadIdx.x;
    if (i >= M4 * Dm) return;
    int m = i >> 9, c = i & 511;
    planewrite(x[i], xt, (long long)m * 1024 + ((c >> 6) * 128 + (c & 63)));
}

// ---------------- RMSNorm -> planes ----------------
__global__ void rmsnorm_t_k(const float* __restrict__ x, const float* __restrict__ w,
                            __nv_bfloat16* __restrict__ xnt) {
    int row = blockIdx.x;
    int tid = threadIdx.x;   // 128
    const float* xr = x + (long long)row * Dm;
    float v[4];
    float s = 0.0f;
#pragma unroll
    for (int i = 0; i < 4; i++) { v[i] = xr[tid + 128 * i]; s += v[i] * v[i]; }
#pragma unroll
    for (int o = 16; o; o >>= 1) s += __shfl_xor_sync(0xffffffffu, s, o);
    __shared__ float ws[4];
    if ((tid & 31) == 0) ws[tid >> 5] = s;
    __syncthreads();
    float tot = ws[0] + ws[1] + ws[2] + ws[3];
    float rs = rsqrtf(tot * (1.0f / Dm) + 1e-5f);
#pragma unroll
    for (int i = 0; i < 4; i++) {
        int c = tid + 128 * i;
        planewrite(v[i] * rs * w[c], xnt, (long long)row * 1024 + ((c >> 6) * 128 + (c & 63)));
    }
}

// ---------------- depthwise causal conv (K=4) + SiLU -> planes ----------------
__global__ void dwconv_k(const float* __restrict__ xz, const float* __restrict__ cw,
                         const float* __restrict__ cb, __nv_bfloat16* __restrict__ xit) {
    int idx = blockIdx.x * 256 + threadIdx.x;
    if (idx >= M4 * DIc) return;
    int d = idx & (DIc - 1);
    int m = idx >> 10;
    int t = m % T4;
    float w0 = cw[d * 4 + 0], w1 = cw[d * 4 + 1], w2 = cw[d * 4 + 2], w3 = cw[d * 4 + 3];
    const float* base = xz + (long long)m * 2048 + d;
    float acc = w3 * base[0];
    if (t >= 1) acc = fmaf(w2, base[-2048], acc);
    if (t >= 2) acc = fmaf(w1, base[-2 * 2048], acc);
    if (t >= 3) acc = fmaf(w0, base[-3 * 2048], acc);
    acc += cb[d];
    float s = acc / (1.0f + expf(-acc));
    planewrite(s, xit, (long long)m * 2048 + ((d >> 6) * 128 + (d & 63)));
}

// ---------------- selective scan (xi from planes) -> yc planes ----------------
__global__ void scan_k(const float* __restrict__ dt, const __nv_bfloat16* __restrict__ xit,
                       const float* __restrict__ proj, const float* __restrict__ xz,
                       const float* __restrict__ A_log, const float* __restrict__ dskip,
                       __nv_bfloat16* __restrict__ yct) {
    int w = (blockIdx.x * blockDim.x + threadIdx.x) >> 5;
    int lane = threadIdx.x & 31;
    int b = w >> 9;
    int dp = w & 511;
    int d = dp * 2 + (lane >> 4);
    int n = lane & 15;
    float Ac = -expf(A_log[d * Nst + n]);
    float dsk = dskip[d];
    float h = 0.0f;
    int mb = b * T4;
    long long xibase = (long long)mb * 2048 + ((d >> 6) * 128 + (d & 63));
    for (int t = 0; t < T4; t++) {
        int m = mb + t;
        float dtv = dt[m * DIc + d];
        long long xio = xibase + (long long)t * 2048;
        float xiv = __bfloat162float(xit[xio]) + __bfloat162float(xit[xio + 64]);
        float Bv = proj[m * 64 + 32 + n];
        float Cv = proj[m * 64 + 48 + n];
        float dA = __expf(dtv * Ac);
        h = fmaf(dA, h, dtv * xiv * Bv);
        float p = h * Cv;
        p += __shfl_xor_sync(0xffffffffu, p, 8);
        p += __shfl_xor_sync(0xffffffffu, p, 4);
        p += __shfl_xor_sync(0xffffffffu, p, 2);
        p += __shfl_xor_sync(0xffffffffu, p, 1);
        if (n == 0) {
            float zv = xz[(long long)m * 2048 + DIc + d];
            float yv = p + dsk * xiv;
            planewrite(yv * zv / (1.0f + __expf(-zv)), yct,
                       (long long)m * 2048 + ((d >> 6) * 128 + (d & 63)));
        }
    }
}

__global__ void lens_k(const int* __restrict__ fl, float* __restrict__ out, int out_size) {
    int b = threadIdx.x;
    if (b < Bsz && out_size >= M4 * Vv + Bsz) {
        int v = fl[b] >> 2;
        if (v < 1) v = 1;
        out[M4 * Vv + b] = (float)v;
    }
}

// ---------------- launcher ----------------
extern "C" void kernel_launch(void* const* d_in, const int* in_sizes, int n_in,
                              void* d_out, int out_size) {
    (void)in_sizes; (void)n_in;
    const float* feats    = (const float*)d_in[0];
    const int*   feat_lens= (const int*)  d_in[1];
    const float* conv1_w  = (const float*)d_in[2];
    const float* conv1_b  = (const float*)d_in[3];
    const float* conv2_w  = (const float*)d_in[4];
    const float* conv2_b  = (const float*)d_in[5];
    const float* norm_w   = (const float*)d_in[6];
    const float* in_proj  = (const float*)d_in[7];
    const float* dwc_w    = (const float*)d_in[8];
    const float* dwc_b    = (const float*)d_in[9];
    const float* x_proj   = (const float*)d_in[10];
    const float* dt_w     = (const float*)d_in[11];
    const float* dt_b     = (const float*)d_in[12];
    const float* A_log    = (const float*)d_in[13];
    const float* D_skip   = (const float*)d_in[14];
    const float* out_proj = (const float*)d_in[15];
    const float* head_w   = (const float*)d_in[16];
    const float* head_b   = (const float*)d_in[17];
    float* out = (float*)d_out;

    void* sym = nullptr;
    cudaGetSymbolAddress(&sym, g_buf);
    float* gb = (float*)sym;
    __nv_bfloat16* featspA = (__nv_bfloat16*)(gb + OFF_FEATSPA);
    __nv_bfloat16* out1p   = (__nv_bfloat16*)(gb + OFF_OUT1P);
    __nv_bfloat16* xn_t    = (__nv_bfloat16*)(gb + OFF_XN_T);
    float*         xz      = gb + OFF_XZ;
    __nv_bfloat16* xi_t    = (__nv_bfloat16*)(gb + OFF_XI_T);
    float*         dtbuf   = gb + OFF_DT;
    float*         proj    = gb + OFF_PROJ;
    __nv_bfloat16* proj_t  = (__nv_bfloat16*)(gb + OFF_PROJ_T);
    __nv_bfloat16* yc_t    = (__nv_bfloat16*)(gb + OFF_YC_T);
    float*         x       = gb + OFF_X;
    __nv_bfloat16* x_t     = (__nv_bfloat16*)(gb + OFF_X_T);
    __nv_bfloat16* w1t     = (__nv_bfloat16*)(gb + OFF_W1T);
    __nv_bfloat16* w2t     = (__nv_bfloat16*)(gb + OFF_W2T);
    __nv_bfloat16* inW     = (__nv_bfloat16*)(gb + OFF_INW);
    __nv_bfloat16* xW      = (__nv_bfloat16*)(gb + OFF_XW);
    __nv_bfloat16* dtW     = (__nv_bfloat16*)(gb + OFF_DTW);
    __nv_bfloat16* outW    = (__nv_bfloat16*)(gb + OFF_OUTW);
    __nv_bfloat16* headW   = (__nv_bfloat16*)(gb + OFF_HEADW);
    float*         xpart   = gb + OFF_XPART;

    const int SMB64  = 1024 + 2 * (16384 + 2 * 64 * 128);    // 66560
    const int SMB128 = 1024 + 2 * (16384 + 2 * 128 * 128);   // 99328
    cudaFuncSetAttribute(bgemm_k<64>,  cudaFuncAttributeMaxDynamicSharedMemorySize, SMB64);
    cudaFuncSetAttribute(bgemm_k<128>, cudaFuncAttributeMaxDynamicSharedMemorySize, SMB128);
    const int BIGK = 1 << 28;

    // ONE fused prep/conversion launch
    prep_all_k<<<(int)((R_TOT + 255LL) / 256), 256>>>(
        feats, conv1_w, conv2_w, head_w, in_proj, x_proj, dt_w, out_proj,
        w1t, w2t, featspA, out1p, headW, inW, xW, dtW, outW);

    // conv1: M=6400, N=512, K=256 -> out1p planes (skip pad row t=0)
    bgemm_k<128><<<dim3(4, 100), 256, SMB128>>>(
        featspA, w1t, conv1_b, out1p + 1024,
        4, 512,
        M2, 0, 512,
        800, 802LL * 1024, 1024,
        1, 1, 0, BIGK, 0);

    // conv2: M=3200, N=512, K=1536 -> x f32
    bgemm_k<64><<<dim3(8, 50), 256, SMB64>>>(
        out1p, w2t, conv2_b, x,
        24, 3072,
        400, 802LL * 1024, 2048,
        M4, 0, 512,
        1, 0, 0, BIGK, 0);

    for (int l = 0; l < Ll; l++) {
        rmsnorm_t_k<<<M4, 128>>>(x, norm_w + l * Dm, xn_t);

        // xz = xn @ in_proj  (3200x2048, K=512)
        bgemm_k<128><<<dim3(16, 50), 256, SMB128>>>(
            xn_t, inW + (size_t)l * S0E, nullptr, xz,
            8, 1024,
            M4, 0, 1024,
            M4, 0, 2048,
            0, 0, 0, BIGK, 0);

        dwconv_k<<<(M4 * DIc + 255) / 256, 256>>>(
            xz, dwc_w + l * DIc * 4, dwc_b + l * DIc, xi_t);

        // proj partials = xi @ x_proj  (3200x64, K=1024, split-K x4)
        bgemm_k<64><<<dim3(1, 50, 4), 256, SMB64>>>(
            xi_t, xW + (size_t)l * S1E, nullptr, xpart,
            16, 2048,
            M4, 0, 2048,
            M4, 0, 64,
            0, 0, 0, 4, 204800);

        xcomb_k<<<(M4 * 128 + 255) / 256, 256>>>(xpart, proj, proj_t);

        // dt = softplus(proj @ dt_w + dt_b)  (3200x1024, K=64)
        bgemm_k<128><<<dim3(8, 50), 256, SMB128>>>(
            proj_t, dtW + (size_t)l * S2E, dt_b + l * DIc, dtbuf,
            1, 128,
            M4, 0, 128,
            M4, 0, 1024,
            2, 0, 0, BIGK, 0);

        scan_k<<<512, 256>>>(dtbuf, xi_t, proj, xz,
                             A_log + (size_t)l * DIc * Nst, D_skip + l * DIc, yc_t);

        // x += yc @ out_proj  (3200x512, K=1024)
        bgemm_k<64><<<dim3(8, 50), 256, SMB64>>>(
            yc_t, outW + (size_t)l * S3E, nullptr, x,
            16, 2048,
            M4, 0, 2048,
            M4, 0, 512,
            0, 0, 1, BIGK, 0);
    }

    x_t_k<<<(M4 * Dm + 255) / 256, 256>>>(x, x_t);

    // logits = x @ head_w + head_b  (3200x1024, K=512)
    bgemm_k<128><<<dim3(8, 50), 256, SMB128>>>(
        x_t, headW, head_b, out,
        8, 1024,
        M4, 0, 1024,
        M4, 0, 1024,
        0, 0, 0, BIGK, 0);

    lens_k<<<1, 32>>>(feat_lens, out, out_size);
}